// round 2
// baseline (speedup 1.0000x reference)
#include <cuda_runtime.h>
#include <cuda_bf16.h>
#include <math.h>

#define NN 50000
#define EE 800000
#define EA 850000   // EE + NN self loops
#define HC 128
#define HEADS 4
#define SLOPE 0.2f

// ---------------- scratch (device globals; no allocation allowed) ----------------
// __align__(16): these are accessed via float4 loads and red.global.add.v4.f32.
__device__ __align__(16) float g_h[2][NN * HC];     // ping-pong node features
__device__ __align__(16) float g_xl[NN * HC];
__device__ __align__(16) float g_xr[NN * HC];
__device__ __align__(16) float g_sc[EA * HEADS];    // scores, then exp(score-m)
__device__ __align__(16) float g_m[NN * HEADS];
__device__ __align__(16) float g_s[NN * HEADS];
__device__ __align__(16) int   g_src[EA];
__device__ __align__(16) int   g_dst[EA];
__device__ __align__(16) float g_mlp[NN * 16];      // final 16-dim node features
__device__ int g_is64;

static inline int cdiv(int a, int b) { return (a + b - 1) / b; }

// ---------------- dtype detection: is edge_index int64 or int32? ----------------
__global__ void k_detect(const unsigned int* __restrict__ ei32) {
    // If the buffer really holds int64 values in [0, 50000), every odd 32-bit
    // word (the high half) is 0. If it holds int32 random values in [0,50000),
    // the probability of four being 0 is ~1e-19.
    g_is64 = ((ei32[1] | ei32[3] | ei32[5] | ei32[7]) == 0u) ? 1 : 0;
}

// ---------------- edge prep: -> int32, append self loops -------------------------
__global__ void k_prep(const void* __restrict__ ei) {
    int i = blockIdx.x * blockDim.x + threadIdx.x;
    if (i >= EA) return;
    if (i < EE) {
        int s, d;
        if (g_is64) {
            const long long* p = (const long long*)ei;
            s = (int)p[i];
            d = (int)p[EE + i];
        } else {
            const int* p = (const int*)ei;
            s = p[i];
            d = p[EE + i];
        }
        g_src[i] = s;
        g_dst[i] = d;
    } else {
        g_src[i] = i - EE;
        g_dst[i] = i - EE;
    }
}

// ---------------- xl = h@Wl+bl, xr = h@Wr+br (256 threads, 32 nodes/block) ------
__global__ void __launch_bounds__(256) k_gemm(const float* __restrict__ hin,
                                              const float* __restrict__ Wl,
                                              const float* __restrict__ Wr,
                                              const float* __restrict__ bl,
                                              const float* __restrict__ br) {
    __shared__ float4 sh[32][32];   // 32 nodes x 128 floats
    int t = threadIdx.x;
    int nb = blockIdx.x * 32;
    const float4* hin4 = (const float4*)hin;
    #pragma unroll
    for (int r = 0; r < 4; r++) {
        int p = r * 256 + t;        // 0..1023
        int n = p >> 5, k4 = p & 31;
        int gn = nb + n;
        float4 v = make_float4(0.f, 0.f, 0.f, 0.f);
        if (gn < NN) v = hin4[(size_t)gn * 32 + k4];
        sh[n][k4] = v;
    }
    __syncthreads();

    int col = t & 127;
    const float* W = (t < 128) ? Wl : Wr;
    float* outp    = (t < 128) ? g_xl : g_xr;
    float bias     = (t < 128) ? bl[col] : br[col];

    float acc[32];
    #pragma unroll
    for (int n = 0; n < 32; n++) acc[n] = bias;

    #pragma unroll 4
    for (int k4 = 0; k4 < 32; k4++) {
        float w0 = W[(k4 * 4 + 0) * 128 + col];
        float w1 = W[(k4 * 4 + 1) * 128 + col];
        float w2 = W[(k4 * 4 + 2) * 128 + col];
        float w3 = W[(k4 * 4 + 3) * 128 + col];
        #pragma unroll
        for (int n = 0; n < 32; n++) {
            float4 h = sh[n][k4];
            acc[n] = fmaf(h.x, w0, acc[n]);
            acc[n] = fmaf(h.y, w1, acc[n]);
            acc[n] = fmaf(h.z, w2, acc[n]);
            acc[n] = fmaf(h.w, w3, acc[n]);
        }
    }
    #pragma unroll
    for (int n = 0; n < 32; n++) {
        int gn = nb + n;
        if (gn < NN) outp[(size_t)gn * 128 + col] = acc[n];
    }
}

// ---------------- init m/s and zero the accumulation buffer --------------------
__global__ void k_init(float* __restrict__ hnext) {
    int i = blockIdx.x * blockDim.x + threadIdx.x;
    if (i < NN * HC) hnext[i] = 0.f;
    if (i < NN * HEADS) { g_m[i] = -3.4e38f; g_s[i] = 0.f; }
}

__device__ __forceinline__ void atomicMaxFloat(float* addr, float v) {
    if (v >= 0.f) atomicMax((int*)addr, __float_as_int(v));
    else          atomicMin((unsigned int*)addr, __float_as_uint(v));
}

// ---------------- score pass: one warp per edge --------------------------------
__global__ void __launch_bounds__(256) k_score(const float* __restrict__ att) {
    int gid = blockIdx.x * blockDim.x + threadIdx.x;
    int e = gid >> 5, lane = gid & 31;
    if (e >= EA) return;
    int s = g_src[e], d = g_dst[e];
    const float4* xl4 = (const float4*)g_xl;
    const float4* xr4 = (const float4*)g_xr;
    float4 a = xl4[(size_t)s * 32 + lane];
    float4 b = xr4[(size_t)d * 32 + lane];
    float4 w = ((const float4*)att)[lane];
    float vx = a.x + b.x, vy = a.y + b.y, vz = a.z + b.z, vw = a.w + b.w;
    vx = fmaxf(vx, SLOPE * vx);
    vy = fmaxf(vy, SLOPE * vy);
    vz = fmaxf(vz, SLOPE * vz);
    vw = fmaxf(vw, SLOPE * vw);
    float p = vx * w.x + vy * w.y + vz * w.z + vw * w.w;
    p += __shfl_xor_sync(0xffffffffu, p, 1);
    p += __shfl_xor_sync(0xffffffffu, p, 2);
    p += __shfl_xor_sync(0xffffffffu, p, 4);
    if ((lane & 7) == 0) {
        int h = lane >> 3;
        g_sc[(size_t)e * 4 + h] = p;
        atomicMaxFloat(&g_m[d * 4 + h], p);
    }
}

// ---------------- exp + segment sum: one thread per (edge, head) ---------------
__global__ void k_exp() {
    int i = blockIdx.x * blockDim.x + threadIdx.x;
    if (i >= EA * HEADS) return;
    int e = i >> 2, h = i & 3;
    int d = g_dst[e];
    float ex = __expf(g_sc[i] - g_m[d * 4 + h]);
    g_sc[i] = ex;
    atomicAdd(&g_s[d * 4 + h], ex);
}

// ---------------- aggregation: one warp per edge, vectorized RED ---------------
__global__ void __launch_bounds__(256) k_agg(float* __restrict__ hnext) {
    int gid = blockIdx.x * blockDim.x + threadIdx.x;
    int e = gid >> 5, lane = gid & 31;
    if (e >= EA) return;
    int s = g_src[e], d = g_dst[e];
    int h = lane >> 3;
    float alpha = __fdividef(g_sc[(size_t)e * 4 + h], g_s[d * 4 + h] + 1e-16f);
    float4 a = ((const float4*)g_xl)[(size_t)s * 32 + lane];
    float4 v = make_float4(alpha * a.x, alpha * a.y, alpha * a.z, alpha * a.w);
    float4* dst = ((float4*)hnext) + (size_t)d * 32 + lane;
    asm volatile("red.global.add.v4.f32 [%0], {%1,%2,%3,%4};"
                 :: "l"(dst), "f"(v.x), "f"(v.y), "f"(v.z), "f"(v.w)
                 : "memory");
}

// ---------------- bias + relu in place ------------------------------------------
__global__ void k_fin(float* __restrict__ h, const float* __restrict__ cb) {
    int i = blockIdx.x * blockDim.x + threadIdx.x;
    if (i >= NN * HC) return;
    h[i] = fmaxf(h[i] + cb[i & 127], 0.f);
}

// ---------------- fused MLP: relu(h@W1+b1) -> relu(@W2+b2) ----------------------
__global__ void __launch_bounds__(128) k_mlp(const float* __restrict__ hin,
                                             const float* __restrict__ W1,
                                             const float* __restrict__ b1,
                                             const float* __restrict__ W2,
                                             const float* __restrict__ b2) {
    __shared__ float4 sh[16][32];
    __shared__ float  s1[16][33];
    int t = threadIdx.x;
    int nb = blockIdx.x * 16;       // NN % 16 == 0
    const float4* hin4 = (const float4*)hin;
    #pragma unroll
    for (int r = 0; r < 4; r++) {
        int p = r * 128 + t;        // 0..511
        int n = p >> 5, k4 = p & 31;
        sh[n][k4] = hin4[(size_t)(nb + n) * 32 + k4];
    }
    __syncthreads();
    {
        int c = t & 31, n0 = t >> 5;
        #pragma unroll
        for (int rep = 0; rep < 4; rep++) {
            int n = n0 + rep * 4;
            float acc = b1[c];
            #pragma unroll 8
            for (int k4 = 0; k4 < 32; k4++) {
                float4 h = sh[n][k4];
                acc = fmaf(h.x, W1[(k4 * 4 + 0) * 32 + c], acc);
                acc = fmaf(h.y, W1[(k4 * 4 + 1) * 32 + c], acc);
                acc = fmaf(h.z, W1[(k4 * 4 + 2) * 32 + c], acc);
                acc = fmaf(h.w, W1[(k4 * 4 + 3) * 32 + c], acc);
            }
            s1[n][c] = fmaxf(acc, 0.f);
        }
    }
    __syncthreads();
    {
        int c = t & 15, n0 = t >> 4;
        #pragma unroll
        for (int rep = 0; rep < 2; rep++) {
            int n = n0 + rep * 8;
            float acc = b2[c];
            #pragma unroll
            for (int k = 0; k < 32; k++)
                acc = fmaf(s1[n][k], W2[k * 16 + c], acc);
            g_mlp[(size_t)(nb + n) * 16 + c] = fmaxf(acc, 0.f);
        }
    }
}

// ---------------- edge head: e = concat(h[src], h[dst]); out = e@W3+b3 ----------
__global__ void __launch_bounds__(256) k_eout(const float* __restrict__ W3,
                                              const float* __restrict__ b3,
                                              float* __restrict__ outp,
                                              float* __restrict__ eoutp) {
    int gid = blockIdx.x * blockDim.x + threadIdx.x;
    int e = gid >> 5, lane = gid & 31;
    if (e >= EE) return;
    int node = (lane < 16) ? g_src[e] : g_dst[e];
    float v = g_mlp[(size_t)node * 16 + (lane & 15)];
    eoutp[(size_t)e * 32 + lane] = v;
    float a0 = v * W3[lane * 6 + 0];
    float a1 = v * W3[lane * 6 + 1];
    float a2 = v * W3[lane * 6 + 2];
    float a3 = v * W3[lane * 6 + 3];
    float a4 = v * W3[lane * 6 + 4];
    float a5 = v * W3[lane * 6 + 5];
    #pragma unroll
    for (int off = 16; off >= 1; off >>= 1) {
        a0 += __shfl_xor_sync(0xffffffffu, a0, off);
        a1 += __shfl_xor_sync(0xffffffffu, a1, off);
        a2 += __shfl_xor_sync(0xffffffffu, a2, off);
        a3 += __shfl_xor_sync(0xffffffffu, a3, off);
        a4 += __shfl_xor_sync(0xffffffffu, a4, off);
        a5 += __shfl_xor_sync(0xffffffffu, a5, off);
    }
    if (lane == 0) {
        float* o = outp + (size_t)e * 6;
        o[0] = a0 + b3[0];
        o[1] = a1 + b3[1];
        o[2] = a2 + b3[2];
        o[3] = a3 + b3[3];
        o[4] = a4 + b3[4];
        o[5] = a5 + b3[5];
    }
}

// ---------------- launch ---------------------------------------------------------
extern "C" void kernel_launch(void* const* d_in, const int* in_sizes, int n_in,
                              void* d_out, int out_size) {
    const float* x   = (const float*)d_in[0];
    const void*  ei  = d_in[1];
    // d_in[2] = batch (unused)
    const float* Wl  = (const float*)d_in[3];
    const float* Wr  = (const float*)d_in[4];
    const float* bl  = (const float*)d_in[5];
    const float* br  = (const float*)d_in[6];
    const float* att = (const float*)d_in[7];
    const float* cb  = (const float*)d_in[8];
    const float* W1  = (const float*)d_in[9];
    const float* b1  = (const float*)d_in[10];
    const float* W2  = (const float*)d_in[11];
    const float* b2  = (const float*)d_in[12];
    const float* W3  = (const float*)d_in[13];
    const float* b3  = (const float*)d_in[14];

    float* outp  = (float*)d_out;                   // [E, 6]
    float* eoutp = outp + (size_t)EE * 6;           // [E, 32]

    void* hsym = nullptr;
    cudaGetSymbolAddress(&hsym, g_h);
    float* hb0 = (float*)hsym;
    float* hb1 = hb0 + (size_t)NN * HC;

    k_detect<<<1, 1>>>((const unsigned int*)ei);
    k_prep<<<cdiv(EA, 256), 256>>>(ei);

    const float* hin = x;
    float* hbuf[3] = {hb0, hb1, hb0};
    for (int i = 0; i < 3; i++) {
        float* hnext = hbuf[i];
        k_gemm<<<cdiv(NN, 32), 256>>>(hin,
                                      Wl + (size_t)i * 128 * 128,
                                      Wr + (size_t)i * 128 * 128,
                                      bl + (size_t)i * 128,
                                      br + (size_t)i * 128);
        k_init<<<cdiv(NN * HC, 256), 256>>>(hnext);
        k_score<<<cdiv(EA * 32, 256), 256>>>(att + (size_t)i * 128);
        k_exp<<<cdiv(EA * 4, 256), 256>>>();
        k_agg<<<cdiv(EA * 32, 256), 256>>>(hnext);
        k_fin<<<cdiv(NN * HC, 256), 256>>>(hnext, cb + (size_t)i * 128);
        hin = hnext;
    }

    k_mlp<<<NN / 16, 128>>>(hin, W1, b1, W2, b2);
    k_eout<<<cdiv(EE * 32, 256), 256>>>(W3, b3, outp, eoutp);
}

// round 3
// speedup vs baseline: 1.4579x; 1.4579x over previous
#include <cuda_runtime.h>
#include <cuda_bf16.h>
#include <math.h>

#define NN 50000
#define EE 800000
#define EA 850000   // EE + NN self loops
#define HC 128
#define HEADS 4
#define SLOPE 0.2f

// ---------------- scratch (device globals; no allocation allowed) ----------------
__device__ __align__(16) float g_h[2][NN * HC];     // ping-pong node features
__device__ __align__(16) float g_xl[NN * HC];
__device__ __align__(16) float g_xr[NN * HC];
__device__ __align__(16) int   g_src[EA];
__device__ __align__(16) int   g_dst[EA];
__device__ __align__(16) int   g_csr[EA];           // src ids grouped by dst
__device__ __align__(16) int   g_off[NN + 1];       // CSR offsets
__device__ __align__(16) int   g_cnt[NN];
__device__ __align__(16) int   g_cur[NN];
__device__ __align__(16) float g_mlp[NN * 16];      // final 16-dim node features
__device__ int g_is64;

static inline int cdiv(int a, int b) { return (a + b - 1) / b; }

__device__ __forceinline__ void fma2(unsigned long long& d,
                                     unsigned long long a,
                                     unsigned long long b) {
    asm("fma.rn.f32x2 %0, %1, %2, %0;" : "+l"(d) : "l"(a), "l"(b));
}

// ---------------- dtype detection: is edge_index int64 or int32? ----------------
__global__ void k_detect(const unsigned int* __restrict__ ei32) {
    g_is64 = ((ei32[1] | ei32[3] | ei32[5] | ei32[7]) == 0u) ? 1 : 0;
}

__global__ void k_zero() {
    int i = blockIdx.x * blockDim.x + threadIdx.x;
    if (i < NN) g_cnt[i] = 0;
}

// ---------------- edge prep: -> int32, self loops, dst histogram ----------------
__global__ void k_prep(const void* __restrict__ ei) {
    int i = blockIdx.x * blockDim.x + threadIdx.x;
    if (i >= EA) return;
    int s, d;
    if (i < EE) {
        if (g_is64) {
            const long long* p = (const long long*)ei;
            s = (int)p[i];
            d = (int)p[EE + i];
        } else {
            const int* p = (const int*)ei;
            s = p[i];
            d = p[EE + i];
        }
    } else {
        s = i - EE;
        d = i - EE;
    }
    g_src[i] = s;
    g_dst[i] = d;
    atomicAdd(&g_cnt[d], 1);
}

// ---------------- exclusive scan over counts (single block) ---------------------
__global__ void __launch_bounds__(1024) k_scan() {
    __shared__ int ps[1024];
    int t = threadIdx.x;
    const int CH = (NN + 1023) / 1024;  // 49
    int b = t * CH;
    int e = min(b + CH, NN);
    int sum = 0;
    for (int i = b; i < e; i++) sum += g_cnt[i];
    ps[t] = sum;
    __syncthreads();
    for (int off = 1; off < 1024; off <<= 1) {
        int v = (t >= off) ? ps[t - off] : 0;
        __syncthreads();
        ps[t] += v;
        __syncthreads();
    }
    int run = (t == 0) ? 0 : ps[t - 1];
    for (int i = b; i < e; i++) {
        g_off[i] = run;
        g_cur[i] = run;
        run += g_cnt[i];
    }
    if (t == 0) g_off[NN] = EA;
}

__global__ void k_scatter() {
    int i = blockIdx.x * blockDim.x + threadIdx.x;
    if (i >= EA) return;
    int pos = atomicAdd(&g_cur[g_dst[i]], 1);
    g_csr[pos] = g_src[i];
}

// ---------------- xl = h@Wl+bl, xr = h@Wr+br; packed f32x2 FMA -------------------
__global__ void __launch_bounds__(256) k_gemm(const float* __restrict__ hin,
                                              const float* __restrict__ Wl,
                                              const float* __restrict__ Wr,
                                              const float* __restrict__ bl,
                                              const float* __restrict__ br) {
    __shared__ float4 sh[32][32];   // 32 nodes x 128 floats
    int t = threadIdx.x;
    int nb = blockIdx.x * 32;
    const float4* hin4 = (const float4*)hin;
    #pragma unroll
    for (int r = 0; r < 4; r++) {
        int p = r * 256 + t;        // 0..1023
        int n = p >> 5, k4 = p & 31;
        int gn = nb + n;
        float4 v = make_float4(0.f, 0.f, 0.f, 0.f);
        if (gn < NN) v = hin4[(size_t)gn * 32 + k4];
        sh[n][k4] = v;
    }
    __syncthreads();

    int col = t & 127;
    const float* W = (t < 128) ? Wl : Wr;
    float* outp    = (t < 128) ? g_xl : g_xr;
    float bias     = (t < 128) ? bl[col] : br[col];

    unsigned long long acc[32];
    #pragma unroll
    for (int n = 0; n < 32; n++) acc[n] = 0ull;

    #pragma unroll 2
    for (int k4 = 0; k4 < 32; k4++) {
        float w0 = W[(k4 * 4 + 0) * 128 + col];
        float w1 = W[(k4 * 4 + 1) * 128 + col];
        float w2 = W[(k4 * 4 + 2) * 128 + col];
        float w3 = W[(k4 * 4 + 3) * 128 + col];
        unsigned long long wp01, wp23;
        asm("mov.b64 %0, {%1, %2};" : "=l"(wp01) : "f"(w0), "f"(w1));
        asm("mov.b64 %0, {%1, %2};" : "=l"(wp23) : "f"(w2), "f"(w3));
        #pragma unroll
        for (int n = 0; n < 32; n++) {
            ulonglong2 hv = *(const ulonglong2*)&sh[n][k4];
            fma2(acc[n], hv.x, wp01);   // k0,k1 partials
            fma2(acc[n], hv.y, wp23);   // k2,k3 partials
        }
    }
    #pragma unroll
    for (int n = 0; n < 32; n++) {
        int gn = nb + n;
        if (gn < NN) {
            float lo, hi;
            asm("mov.b64 {%0, %1}, %2;" : "=f"(lo), "=f"(hi) : "l"(acc[n]));
            outp[(size_t)gn * 128 + col] = lo + hi + bias;
        }
    }
}

// ---------------- fused edge pass: online softmax + aggregate + bias + relu -----
// one warp per destination node
__global__ void __launch_bounds__(256) k_edge(const float* __restrict__ att,
                                              const float* __restrict__ cb,
                                              float* __restrict__ hnext) {
    int gid = blockIdx.x * blockDim.x + threadIdx.x;
    int n = gid >> 5, lane = gid & 31;
    if (n >= NN) return;
    const float4* xl4 = (const float4*)g_xl;
    float4 xr = ((const float4*)g_xr)[(size_t)n * 32 + lane];
    float4 w  = ((const float4*)att)[lane];
    int beg = g_off[n], end = g_off[n + 1];

    float m = -1e30f, s = 0.f;
    float4 acc = make_float4(0.f, 0.f, 0.f, 0.f);

    for (int i = beg; i < end; i++) {
        int src = g_csr[i];
        float4 a = xl4[(size_t)src * 32 + lane];
        float vx = a.x + xr.x, vy = a.y + xr.y, vz = a.z + xr.z, vw = a.w + xr.w;
        vx = fmaxf(vx, SLOPE * vx);
        vy = fmaxf(vy, SLOPE * vy);
        vz = fmaxf(vz, SLOPE * vz);
        vw = fmaxf(vw, SLOPE * vw);
        float p = vx * w.x + vy * w.y + vz * w.z + vw * w.w;
        p += __shfl_xor_sync(0xffffffffu, p, 1);
        p += __shfl_xor_sync(0xffffffffu, p, 2);
        p += __shfl_xor_sync(0xffffffffu, p, 4);   // per-head score, all 8 lanes
        float mn = fmaxf(m, p);
        float scale = __expf(m - mn);
        float t = __expf(p - mn);
        s = s * scale + t;
        acc.x = acc.x * scale + t * a.x;
        acc.y = acc.y * scale + t * a.y;
        acc.z = acc.z * scale + t * a.z;
        acc.w = acc.w * scale + t * a.w;
        m = mn;
    }
    float inv = __fdividef(1.f, s + 1e-16f);
    float4 cbv = ((const float4*)cb)[lane];
    float4 o;
    o.x = fmaxf(fmaf(acc.x, inv, cbv.x), 0.f);
    o.y = fmaxf(fmaf(acc.y, inv, cbv.y), 0.f);
    o.z = fmaxf(fmaf(acc.z, inv, cbv.z), 0.f);
    o.w = fmaxf(fmaf(acc.w, inv, cbv.w), 0.f);
    ((float4*)hnext)[(size_t)n * 32 + lane] = o;
}

// ---------------- fused MLP: relu(h@W1+b1) -> relu(@W2+b2) ----------------------
__global__ void __launch_bounds__(128) k_mlp(const float* __restrict__ hin,
                                             const float* __restrict__ W1,
                                             const float* __restrict__ b1,
                                             const float* __restrict__ W2,
                                             const float* __restrict__ b2) {
    __shared__ float4 sh[16][32];
    __shared__ float  s1[16][33];
    int t = threadIdx.x;
    int nb = blockIdx.x * 16;       // NN % 16 == 0
    const float4* hin4 = (const float4*)hin;
    #pragma unroll
    for (int r = 0; r < 4; r++) {
        int p = r * 128 + t;        // 0..511
        int n = p >> 5, k4 = p & 31;
        sh[n][k4] = hin4[(size_t)(nb + n) * 32 + k4];
    }
    __syncthreads();
    {
        int c = t & 31, n0 = t >> 5;
        #pragma unroll
        for (int rep = 0; rep < 4; rep++) {
            int n = n0 + rep * 4;
            float acc = b1[c];
            #pragma unroll 8
            for (int k4 = 0; k4 < 32; k4++) {
                float4 h = sh[n][k4];
                acc = fmaf(h.x, W1[(k4 * 4 + 0) * 32 + c], acc);
                acc = fmaf(h.y, W1[(k4 * 4 + 1) * 32 + c], acc);
                acc = fmaf(h.z, W1[(k4 * 4 + 2) * 32 + c], acc);
                acc = fmaf(h.w, W1[(k4 * 4 + 3) * 32 + c], acc);
            }
            s1[n][c] = fmaxf(acc, 0.f);
        }
    }
    __syncthreads();
    {
        int c = t & 15, n0 = t >> 4;
        #pragma unroll
        for (int rep = 0; rep < 2; rep++) {
            int n = n0 + rep * 8;
            float acc = b2[c];
            #pragma unroll
            for (int k = 0; k < 32; k++)
                acc = fmaf(s1[n][k], W2[k * 16 + c], acc);
            g_mlp[(size_t)(nb + n) * 16 + c] = fmaxf(acc, 0.f);
        }
    }
}

// ---------------- edge head: e = concat(h[src], h[dst]); out = e@W3+b3 ----------
__global__ void __launch_bounds__(256) k_eout(const float* __restrict__ W3,
                                              const float* __restrict__ b3,
                                              float* __restrict__ outp,
                                              float* __restrict__ eoutp) {
    int gid = blockIdx.x * blockDim.x + threadIdx.x;
    int e = gid >> 5, lane = gid & 31;
    if (e >= EE) return;
    int node = (lane < 16) ? g_src[e] : g_dst[e];
    float v = g_mlp[(size_t)node * 16 + (lane & 15)];
    eoutp[(size_t)e * 32 + lane] = v;
    float a0 = v * W3[lane * 6 + 0];
    float a1 = v * W3[lane * 6 + 1];
    float a2 = v * W3[lane * 6 + 2];
    float a3 = v * W3[lane * 6 + 3];
    float a4 = v * W3[lane * 6 + 4];
    float a5 = v * W3[lane * 6 + 5];
    #pragma unroll
    for (int off = 16; off >= 1; off >>= 1) {
        a0 += __shfl_xor_sync(0xffffffffu, a0, off);
        a1 += __shfl_xor_sync(0xffffffffu, a1, off);
        a2 += __shfl_xor_sync(0xffffffffu, a2, off);
        a3 += __shfl_xor_sync(0xffffffffu, a3, off);
        a4 += __shfl_xor_sync(0xffffffffu, a4, off);
        a5 += __shfl_xor_sync(0xffffffffu, a5, off);
    }
    if (lane == 0) {
        float* o = outp + (size_t)e * 6;
        o[0] = a0 + b3[0];
        o[1] = a1 + b3[1];
        o[2] = a2 + b3[2];
        o[3] = a3 + b3[3];
        o[4] = a4 + b3[4];
        o[5] = a5 + b3[5];
    }
}

// ---------------- launch ---------------------------------------------------------
extern "C" void kernel_launch(void* const* d_in, const int* in_sizes, int n_in,
                              void* d_out, int out_size) {
    const float* x   = (const float*)d_in[0];
    const void*  ei  = d_in[1];
    // d_in[2] = batch (unused)
    const float* Wl  = (const float*)d_in[3];
    const float* Wr  = (const float*)d_in[4];
    const float* bl  = (const float*)d_in[5];
    const float* br  = (const float*)d_in[6];
    const float* att = (const float*)d_in[7];
    const float* cb  = (const float*)d_in[8];
    const float* W1  = (const float*)d_in[9];
    const float* b1  = (const float*)d_in[10];
    const float* W2  = (const float*)d_in[11];
    const float* b2  = (const float*)d_in[12];
    const float* W3  = (const float*)d_in[13];
    const float* b3  = (const float*)d_in[14];

    float* outp  = (float*)d_out;                   // [E, 6]
    float* eoutp = outp + (size_t)EE * 6;           // [E, 32]

    void* hsym = nullptr;
    cudaGetSymbolAddress(&hsym, g_h);
    float* hb0 = (float*)hsym;
    float* hb1 = hb0 + (size_t)NN * HC;

    k_detect<<<1, 1>>>((const unsigned int*)ei);
    k_zero<<<cdiv(NN, 256), 256>>>();
    k_prep<<<cdiv(EA, 256), 256>>>(ei);
    k_scan<<<1, 1024>>>();
    k_scatter<<<cdiv(EA, 256), 256>>>();

    const float* hin = x;
    float* hbuf[3] = {hb0, hb1, hb0};
    for (int i = 0; i < 3; i++) {
        float* hnext = hbuf[i];
        k_gemm<<<cdiv(NN, 32), 256>>>(hin,
                                      Wl + (size_t)i * 128 * 128,
                                      Wr + (size_t)i * 128 * 128,
                                      bl + (size_t)i * 128,
                                      br + (size_t)i * 128);
        k_edge<<<cdiv(NN * 32, 256), 256>>>(att + (size_t)i * 128,
                                            cb + (size_t)i * 128, hnext);
        hin = hnext;
    }

    k_mlp<<<NN / 16, 128>>>(hin, W1, b1, W2, b2);
    k_eout<<<cdiv(EE * 32, 256), 256>>>(W3, b3, outp, eoutp);
}

// round 4
// speedup vs baseline: 1.7354x; 1.1903x over previous
#include <cuda_runtime.h>
#include <cuda_bf16.h>
#include <math.h>

#define NN 50000
#define EE 800000
#define EA 850000   // EE + NN self loops
#define HC 128
#define HEADS 4
#define SLOPE 0.2f
#define SCAN_B 200  // scan blocks (200*256 = 51200 >= NN)

// ---------------- scratch (device globals; no allocation allowed) ----------------
__device__ __align__(16) float g_h[2][NN * HC];     // ping-pong node features
__device__ __align__(16) float g_xl[NN * HC];
__device__ __align__(16) float g_xr[NN * HC];
__device__ __align__(16) int   g_src[EA];
__device__ __align__(16) int   g_dst[EA];
__device__ __align__(16) int   g_csr[EA];           // src ids grouped by dst
__device__ __align__(16) int   g_off[NN + 1];       // CSR offsets
__device__ __align__(16) int   g_cnt[NN];
__device__ __align__(16) int   g_cur[NN];
__device__ __align__(16) int   g_bsum[256];
__device__ __align__(16) int   g_boff[256];
__device__ __align__(16) float g_mlp[NN * 16];      // final 16-dim node features
__device__ __align__(16) float g_p1[NN * 6];        // h_mlp @ W3[0:16]
__device__ __align__(16) float g_p2[NN * 6];        // h_mlp @ W3[16:32]
__device__ int g_is64;

static inline int cdiv(int a, int b) { return (a + b - 1) / b; }

__device__ __forceinline__ void fma2(unsigned long long& d,
                                     unsigned long long a,
                                     unsigned long long b) {
    asm("fma.rn.f32x2 %0, %1, %2, %0;" : "+l"(d) : "l"(a), "l"(b));
}

// ---------------- zero counters + dtype detection --------------------------------
__global__ void k_zero(const unsigned int* __restrict__ ei32) {
    int i = blockIdx.x * blockDim.x + threadIdx.x;
    if (i < NN) g_cnt[i] = 0;
    if (i == 0)
        g_is64 = ((ei32[1] | ei32[3] | ei32[5] | ei32[7]) == 0u) ? 1 : 0;
}

// ---------------- edge prep: -> int32, self loops, dst histogram ----------------
__global__ void k_prep(const void* __restrict__ ei) {
    int i = blockIdx.x * blockDim.x + threadIdx.x;
    if (i >= EA) return;
    int s, d;
    if (i < EE) {
        if (g_is64) {
            const long long* p = (const long long*)ei;
            s = (int)p[i];
            d = (int)p[EE + i];
        } else {
            const int* p = (const int*)ei;
            s = p[i];
            d = p[EE + i];
        }
    } else {
        s = i - EE;
        d = i - EE;
    }
    g_src[i] = s;
    g_dst[i] = d;
    atomicAdd(&g_cnt[d], 1);
}

// ---------------- decoupled scan: phase 1 (block sums) --------------------------
__global__ void __launch_bounds__(256) k_bsum() {
    int t = threadIdx.x, b = blockIdx.x;
    int i = b * 256 + t;
    int v = (i < NN) ? g_cnt[i] : 0;
    #pragma unroll
    for (int off = 16; off >= 1; off >>= 1)
        v += __shfl_xor_sync(0xffffffffu, v, off);
    __shared__ int ws[8];
    if ((t & 31) == 0) ws[t >> 5] = v;
    __syncthreads();
    if (t == 0) {
        int s = 0;
        #pragma unroll
        for (int w = 0; w < 8; w++) s += ws[w];
        g_bsum[b] = s;
    }
}

// ---------------- phase 2: exclusive scan of 200 block sums (1 block) -----------
__global__ void __launch_bounds__(256) k_bscan() {
    int t = threadIdx.x;
    int lane = t & 31, wid = t >> 5;
    int val = (t < SCAN_B) ? g_bsum[t] : 0;
    int v = val;
    #pragma unroll
    for (int off = 1; off < 32; off <<= 1) {
        int u = __shfl_up_sync(0xffffffffu, v, off);
        if (lane >= off) v += u;
    }
    __shared__ int ws[8];
    if (lane == 31) ws[wid] = v;
    __syncthreads();
    if (wid == 0) {
        int s = (lane < 8) ? ws[lane] : 0;
        #pragma unroll
        for (int off = 1; off < 8; off <<= 1) {
            int u = __shfl_up_sync(0xffffffffu, s, off);
            if (lane >= off) s += u;
        }
        if (lane < 8) ws[lane] = s;
    }
    __syncthreads();
    int base = (wid > 0) ? ws[wid - 1] : 0;
    g_boff[t] = base + v - val;   // exclusive
    if (t == 0) g_off[NN] = EA;
}

// ---------------- phase 3: local scan + global offset ---------------------------
__global__ void __launch_bounds__(256) k_offs() {
    int t = threadIdx.x, b = blockIdx.x;
    int i = b * 256 + t;
    int lane = t & 31, wid = t >> 5;
    int val = (i < NN) ? g_cnt[i] : 0;
    int v = val;
    #pragma unroll
    for (int off = 1; off < 32; off <<= 1) {
        int u = __shfl_up_sync(0xffffffffu, v, off);
        if (lane >= off) v += u;
    }
    __shared__ int ws[8];
    if (lane == 31) ws[wid] = v;
    __syncthreads();
    if (wid == 0) {
        int s = (lane < 8) ? ws[lane] : 0;
        #pragma unroll
        for (int off = 1; off < 8; off <<= 1) {
            int u = __shfl_up_sync(0xffffffffu, s, off);
            if (lane >= off) s += u;
        }
        if (lane < 8) ws[lane] = s;
    }
    __syncthreads();
    int base = ((wid > 0) ? ws[wid - 1] : 0) + g_boff[b];
    if (i < NN) {
        int excl = base + v - val;
        g_off[i] = excl;
        g_cur[i] = excl;
    }
}

__global__ void k_scatter() {
    int i = blockIdx.x * blockDim.x + threadIdx.x;
    if (i >= EA) return;
    int pos = atomicAdd(&g_cur[g_dst[i]], 1);
    g_csr[pos] = g_src[i];
}

// ---------------- xl = h@Wl+bl, xr = h@Wr+br; packed f32x2 FMA -------------------
__global__ void __launch_bounds__(256) k_gemm(const float* __restrict__ hin,
                                              const float* __restrict__ Wl,
                                              const float* __restrict__ Wr,
                                              const float* __restrict__ bl,
                                              const float* __restrict__ br) {
    __shared__ float4 sh[32][32];   // 32 nodes x 128 floats
    int t = threadIdx.x;
    int nb = blockIdx.x * 32;
    const float4* hin4 = (const float4*)hin;
    #pragma unroll
    for (int r = 0; r < 4; r++) {
        int p = r * 256 + t;        // 0..1023
        int n = p >> 5, k4 = p & 31;
        int gn = nb + n;
        float4 v = make_float4(0.f, 0.f, 0.f, 0.f);
        if (gn < NN) v = hin4[(size_t)gn * 32 + k4];
        sh[n][k4] = v;
    }
    __syncthreads();

    int col = t & 127;
    const float* W = (t < 128) ? Wl : Wr;
    float* outp    = (t < 128) ? g_xl : g_xr;
    float bias     = (t < 128) ? bl[col] : br[col];

    unsigned long long acc[32];
    #pragma unroll
    for (int n = 0; n < 32; n++) acc[n] = 0ull;

    #pragma unroll 2
    for (int k4 = 0; k4 < 32; k4++) {
        float w0 = W[(k4 * 4 + 0) * 128 + col];
        float w1 = W[(k4 * 4 + 1) * 128 + col];
        float w2 = W[(k4 * 4 + 2) * 128 + col];
        float w3 = W[(k4 * 4 + 3) * 128 + col];
        unsigned long long wp01, wp23;
        asm("mov.b64 %0, {%1, %2};" : "=l"(wp01) : "f"(w0), "f"(w1));
        asm("mov.b64 %0, {%1, %2};" : "=l"(wp23) : "f"(w2), "f"(w3));
        #pragma unroll
        for (int n = 0; n < 32; n++) {
            ulonglong2 hv = *(const ulonglong2*)&sh[n][k4];
            fma2(acc[n], hv.x, wp01);   // k0,k1 partials
            fma2(acc[n], hv.y, wp23);   // k2,k3 partials
        }
    }
    #pragma unroll
    for (int n = 0; n < 32; n++) {
        int gn = nb + n;
        if (gn < NN) {
            float lo, hi;
            asm("mov.b64 {%0, %1}, %2;" : "=f"(lo), "=f"(hi) : "l"(acc[n]));
            outp[(size_t)gn * 128 + col] = lo + hi + bias;
        }
    }
}

// ---------------- fused edge pass: online softmax + aggregate + bias + relu -----
// one warp per destination node
__global__ void __launch_bounds__(256) k_edge(const float* __restrict__ att,
                                              const float* __restrict__ cb,
                                              float* __restrict__ hnext) {
    int gid = blockIdx.x * blockDim.x + threadIdx.x;
    int n = gid >> 5, lane = gid & 31;
    if (n >= NN) return;
    const float4* xl4 = (const float4*)g_xl;
    float4 xr = ((const float4*)g_xr)[(size_t)n * 32 + lane];
    float4 w  = ((const float4*)att)[lane];
    int beg = g_off[n], end = g_off[n + 1];

    float m = -1e30f, s = 0.f;
    float4 acc = make_float4(0.f, 0.f, 0.f, 0.f);

    for (int i = beg; i < end; i++) {
        int src = g_csr[i];
        float4 a = xl4[(size_t)src * 32 + lane];
        float vx = a.x + xr.x, vy = a.y + xr.y, vz = a.z + xr.z, vw = a.w + xr.w;
        vx = fmaxf(vx, SLOPE * vx);
        vy = fmaxf(vy, SLOPE * vy);
        vz = fmaxf(vz, SLOPE * vz);
        vw = fmaxf(vw, SLOPE * vw);
        float p = vx * w.x + vy * w.y + vz * w.z + vw * w.w;
        p += __shfl_xor_sync(0xffffffffu, p, 1);
        p += __shfl_xor_sync(0xffffffffu, p, 2);
        p += __shfl_xor_sync(0xffffffffu, p, 4);   // per-head score, all 8 lanes
        float mn = fmaxf(m, p);
        float scale = __expf(m - mn);
        float t = __expf(p - mn);
        s = s * scale + t;
        acc.x = acc.x * scale + t * a.x;
        acc.y = acc.y * scale + t * a.y;
        acc.z = acc.z * scale + t * a.z;
        acc.w = acc.w * scale + t * a.w;
        m = mn;
    }
    float inv = __fdividef(1.f, s + 1e-16f);
    float4 cbv = ((const float4*)cb)[lane];
    float4 o;
    o.x = fmaxf(fmaf(acc.x, inv, cbv.x), 0.f);
    o.y = fmaxf(fmaf(acc.y, inv, cbv.y), 0.f);
    o.z = fmaxf(fmaf(acc.z, inv, cbv.z), 0.f);
    o.w = fmaxf(fmaf(acc.w, inv, cbv.w), 0.f);
    ((float4*)hnext)[(size_t)n * 32 + lane] = o;
}

// ---------------- fused MLP: relu(h@W1+b1) -> relu(@W2+b2) ----------------------
__global__ void __launch_bounds__(128) k_mlp(const float* __restrict__ hin,
                                             const float* __restrict__ W1,
                                             const float* __restrict__ b1,
                                             const float* __restrict__ W2,
                                             const float* __restrict__ b2) {
    __shared__ float4 sh[16][32];
    __shared__ float  s1[16][33];
    int t = threadIdx.x;
    int nb = blockIdx.x * 16;       // NN % 16 == 0
    const float4* hin4 = (const float4*)hin;
    #pragma unroll
    for (int r = 0; r < 4; r++) {
        int p = r * 128 + t;        // 0..511
        int n = p >> 5, k4 = p & 31;
        sh[n][k4] = hin4[(size_t)(nb + n) * 32 + k4];
    }
    __syncthreads();
    {
        int c = t & 31, n0 = t >> 5;
        #pragma unroll
        for (int rep = 0; rep < 4; rep++) {
            int n = n0 + rep * 4;
            float acc = b1[c];
            #pragma unroll 8
            for (int k4 = 0; k4 < 32; k4++) {
                float4 h = sh[n][k4];
                acc = fmaf(h.x, W1[(k4 * 4 + 0) * 32 + c], acc);
                acc = fmaf(h.y, W1[(k4 * 4 + 1) * 32 + c], acc);
                acc = fmaf(h.z, W1[(k4 * 4 + 2) * 32 + c], acc);
                acc = fmaf(h.w, W1[(k4 * 4 + 3) * 32 + c], acc);
            }
            s1[n][c] = fmaxf(acc, 0.f);
        }
    }
    __syncthreads();
    {
        int c = t & 15, n0 = t >> 4;
        #pragma unroll
        for (int rep = 0; rep < 2; rep++) {
            int n = n0 + rep * 8;
            float acc = b2[c];
            #pragma unroll
            for (int k = 0; k < 32; k++)
                acc = fmaf(s1[n][k], W2[k * 16 + c], acc);
            g_mlp[(size_t)(nb + n) * 16 + c] = fmaxf(acc, 0.f);
        }
    }
}

// ---------------- per-node W3 partials: p1 = mlp@W3[0:16], p2 = mlp@W3[16:32] ---
__global__ void __launch_bounds__(256) k_pp(const float* __restrict__ W3) {
    int i = blockIdx.x * blockDim.x + threadIdx.x;   // (n, c)
    if (i >= NN * 6) return;
    int n = i / 6, c = i - n * 6;
    const float* row = g_mlp + (size_t)n * 16;
    float a1 = 0.f, a2 = 0.f;
    #pragma unroll
    for (int k = 0; k < 16; k++) {
        float v = row[k];
        a1 = fmaf(v, W3[k * 6 + c], a1);
        a2 = fmaf(v, W3[(16 + k) * 6 + c], a2);
    }
    g_p1[i] = a1;
    g_p2[i] = a2;
}

// ---------------- edge head: e = concat(h[src], h[dst]); out = p1+p2+b3 ---------
__global__ void __launch_bounds__(256) k_eout(const float* __restrict__ b3,
                                              float* __restrict__ outp,
                                              float* __restrict__ eoutp) {
    int gid = blockIdx.x * blockDim.x + threadIdx.x;
    int e = gid >> 5, lane = gid & 31;
    if (e >= EE) return;
    int s = g_src[e], d = g_dst[e];
    int node = (lane < 16) ? s : d;
    float v = g_mlp[(size_t)node * 16 + (lane & 15)];
    eoutp[(size_t)e * 32 + lane] = v;
    if (lane < 6) {
        float o = g_p1[s * 6 + lane] + g_p2[d * 6 + lane] + b3[lane];
        outp[(size_t)e * 6 + lane] = o;
    }
}

// ---------------- launch ---------------------------------------------------------
extern "C" void kernel_launch(void* const* d_in, const int* in_sizes, int n_in,
                              void* d_out, int out_size) {
    const float* x   = (const float*)d_in[0];
    const void*  ei  = d_in[1];
    // d_in[2] = batch (unused)
    const float* Wl  = (const float*)d_in[3];
    const float* Wr  = (const float*)d_in[4];
    const float* bl  = (const float*)d_in[5];
    const float* br  = (const float*)d_in[6];
    const float* att = (const float*)d_in[7];
    const float* cb  = (const float*)d_in[8];
    const float* W1  = (const float*)d_in[9];
    const float* b1  = (const float*)d_in[10];
    const float* W2  = (const float*)d_in[11];
    const float* b2  = (const float*)d_in[12];
    const float* W3  = (const float*)d_in[13];
    const float* b3  = (const float*)d_in[14];

    float* outp  = (float*)d_out;                   // [E, 6]
    float* eoutp = outp + (size_t)EE * 6;           // [E, 32]

    void* hsym = nullptr;
    cudaGetSymbolAddress(&hsym, g_h);
    float* hb0 = (float*)hsym;
    float* hb1 = hb0 + (size_t)NN * HC;

    k_zero<<<cdiv(NN, 256), 256>>>((const unsigned int*)ei);
    k_prep<<<cdiv(EA, 256), 256>>>(ei);
    k_bsum<<<SCAN_B, 256>>>();
    k_bscan<<<1, 256>>>();
    k_offs<<<SCAN_B, 256>>>();
    k_scatter<<<cdiv(EA, 256), 256>>>();

    const float* hin = x;
    float* hbuf[3] = {hb0, hb1, hb0};
    for (int i = 0; i < 3; i++) {
        float* hnext = hbuf[i];
        k_gemm<<<cdiv(NN, 32), 256>>>(hin,
                                      Wl + (size_t)i * 128 * 128,
                                      Wr + (size_t)i * 128 * 128,
                                      bl + (size_t)i * 128,
                                      br + (size_t)i * 128);
        k_edge<<<cdiv(NN * 32, 256), 256>>>(att + (size_t)i * 128,
                                            cb + (size_t)i * 128, hnext);
        hin = hnext;
    }

    k_mlp<<<NN / 16, 128>>>(hin, W1, b1, W2, b2);
    k_pp<<<cdiv(NN * 6, 256), 256>>>(W3);
    k_eout<<<cdiv(EE * 32, 256), 256>>>(b3, outp, eoutp);
}